// round 13
// baseline (speedup 1.0000x reference)
#include <cuda_runtime.h>
#include <cuda_fp16.h>
#include <cstdint>

// out[b] = T[fwd_steps[b]-1] @ x[b];  B=128, D=1024, fp32.
// R12: fp16 mma.sync, CTA tile 128x256, warp tile 64x64 (8 warps, 2m x 4n),
// BK=64 chunks (16 barriers), register-double-buffered ldsm fragments,
// 3-stage cp.async. Prepass converts T,x to fp16 planes (16B stores).

#define DDIM 1024
#define BKF 64
#define NCH (DDIM / BKF)          // 16 chunks
#define NSTAGE 3
#define TM 128
#define TN 256

#define A_STR 144                 // bytes per A smem row (64 fp16 + 16 pad)
#define B_STR 528                 // bytes per B smem row (256 fp16 + 16 pad)
#define B_OFF 18432               // B base within stage (128*144)
#define STAGE 52224               // 18432 + 64*528
#define SMEM_TOTAL (NSTAGE * STAGE)  // 156672

// ---- device scratch: fp16 planes ----
__device__ __align__(16) __half g_Th[100ull * DDIM * DDIM];   // 200 MB
__device__ __align__(16) __half g_Xh[128ull * DDIM * DDIM];   // 256 MB

__device__ __forceinline__ uint32_t smem_u32(const void* p) {
    uint32_t a;
    asm("{ .reg .u64 t; cvta.to.shared.u64 t, %1; cvt.u32.u64 %0, t; }" : "=r"(a) : "l"(p));
    return a;
}
__device__ __forceinline__ void cp16(uint32_t dst, const void* src) {
    asm volatile("cp.async.cg.shared.global [%0], [%1], 16;"
                 :: "r"(dst), "l"(src) : "memory");
}
__device__ __forceinline__ void ldsm4(uint32_t (&r)[4], uint32_t addr) {
    asm volatile("ldmatrix.sync.aligned.m8n8.x4.shared.b16 {%0,%1,%2,%3}, [%4];"
                 : "=r"(r[0]), "=r"(r[1]), "=r"(r[2]), "=r"(r[3]) : "r"(addr));
}
__device__ __forceinline__ void ldsm4t(uint32_t (&r)[4], uint32_t addr) {
    asm volatile("ldmatrix.sync.aligned.m8n8.x4.trans.shared.b16 {%0,%1,%2,%3}, [%4];"
                 : "=r"(r[0]), "=r"(r[1]), "=r"(r[2]), "=r"(r[3]) : "r"(addr));
}
__device__ __forceinline__ void mma_f16(float (&d)[4], const uint32_t (&a)[4],
                                        uint32_t b0, uint32_t b1) {
    asm volatile(
        "mma.sync.aligned.m16n8k16.row.col.f32.f16.f16.f32 "
        "{%0,%1,%2,%3}, {%4,%5,%6,%7}, {%8,%9}, {%0,%1,%2,%3};"
        : "+f"(d[0]), "+f"(d[1]), "+f"(d[2]), "+f"(d[3])
        : "r"(a[0]), "r"(a[1]), "r"(a[2]), "r"(a[3]), "r"(b0), "r"(b1));
}

// ---- prepass: fp32 -> fp16, 8 elems/thread, 16B stores ----
__device__ __forceinline__ uint32_t pack2(float x, float y) {
    __half2 h = __floats2half2_rn(x, y);
    return *reinterpret_cast<uint32_t*>(&h);
}
__global__ __launch_bounds__(256) void cvt_T_kernel(const float* __restrict__ src) {
    const size_t i = (size_t)blockIdx.x * blockDim.x + threadIdx.x;  // 8-elem index
    float4 v0 = *reinterpret_cast<const float4*>(src + 8 * i);
    float4 v1 = *reinterpret_cast<const float4*>(src + 8 * i + 4);
    *reinterpret_cast<uint4*>(g_Th + 8 * i) =
        make_uint4(pack2(v0.x, v0.y), pack2(v0.z, v0.w),
                   pack2(v1.x, v1.y), pack2(v1.z, v1.w));
}
__global__ __launch_bounds__(256) void cvt_X_kernel(const float* __restrict__ src) {
    const size_t i = (size_t)blockIdx.x * blockDim.x + threadIdx.x;
    float4 v0 = *reinterpret_cast<const float4*>(src + 8 * i);
    float4 v1 = *reinterpret_cast<const float4*>(src + 8 * i + 4);
    *reinterpret_cast<uint4*>(g_Xh + 8 * i) =
        make_uint4(pack2(v0.x, v0.y), pack2(v0.z, v0.w),
                   pack2(v1.x, v1.y), pack2(v1.z, v1.w));
}

// ---- main GEMM ----
__device__ __forceinline__ void load_stage(
    uint32_t sb, int stage, int kc, int tid, int tm0, int tn0,
    const __half* __restrict__ Ah, const __half* __restrict__ Bh) {
    const uint32_t base = sb + (uint32_t)stage * STAGE;
    // A: 128 rows x 128B -> 1024 x 16B chunks, 4 per thread
    #pragma unroll
    for (int j = 0; j < 4; ++j) {
        const int i = tid * 4 + j;
        const int row = i >> 3, c16 = i & 7;
        cp16(base + row * A_STR + c16 * 16,
             Ah + (size_t)(tm0 + row) * DDIM + kc + c16 * 8);
    }
    // B: 64 rows x 512B -> 2048 x 16B chunks, 8 per thread
    #pragma unroll
    for (int j = 0; j < 8; ++j) {
        const int i = tid * 8 + j;
        const int row = i >> 5, ch = i & 31;
        cp16(base + B_OFF + row * B_STR + ch * 16,
             Bh + (size_t)(kc + row) * DDIM + tn0 + ch * 8);
    }
}

// fragment load for one k16 step: 4 ldsm (A) + 4 ldsm.trans (B)
__device__ __forceinline__ void load_frags(
    uint32_t (&a)[4][4], uint32_t (&bh)[4][4],
    uint32_t sb, uint32_t stg, int k16, int warp_m, int warp_n, int lane) {
    const uint32_t lrow = lane & 15;
    const uint32_t lsel = lane >> 4;
    const uint32_t a_off = sb + stg + (warp_m * 64 + lrow) * A_STR +
                           (k16 * 16 + lsel * 8) * 2;
    const uint32_t b_off = sb + stg + B_OFF + (k16 * 16 + lrow) * B_STR +
                           (warp_n * 64 + lsel * 8) * 2;
    #pragma unroll
    for (int g = 0; g < 4; ++g) ldsm4t(bh[g], b_off + g * 32);
    #pragma unroll
    for (int mt = 0; mt < 4; ++mt) ldsm4(a[mt], a_off + mt * (16 * A_STR));
}

__device__ __forceinline__ void mma_frags(float (&acc)[4][8][4],
                                          const uint32_t (&a)[4][4],
                                          const uint32_t (&bh)[4][4]) {
    #pragma unroll
    for (int mt = 0; mt < 4; ++mt)
        #pragma unroll
        for (int nt = 0; nt < 8; ++nt)
            mma_f16(acc[mt][nt], a[mt],
                    bh[nt >> 1][(nt & 1) * 2], bh[nt >> 1][(nt & 1) * 2 + 1]);
}

__global__ __launch_bounds__(256) void bgemm_mma_kernel(
    const int* __restrict__ steps32,
    float*     __restrict__ Out) {
    extern __shared__ char smem[];
    const uint32_t sb = smem_u32(smem);
    const int tid  = threadIdx.x;
    const int lane = tid & 31;
    const int wid  = tid >> 5;
    const int warp_m = wid & 1;   // 2 warps over M (64 each)
    const int warp_n = wid >> 1;  // 4 warps over N (64 each)

    const int b = blockIdx.z;
    const bool is64 = (steps32[1] == 0);
    const int kidx = (is64 ? steps32[2 * b] : steps32[b]) - 1;

    const __half* __restrict__ Ah = g_Th + ((size_t)kidx << 20);
    const __half* __restrict__ Bh = g_Xh + ((size_t)b << 20);
    float* __restrict__ Cg = Out + ((size_t)b << 20);

    const int tm0 = blockIdx.y * TM;
    const int tn0 = blockIdx.x * TN;

    float acc[4][8][4];
    #pragma unroll
    for (int i = 0; i < 4; ++i)
        #pragma unroll
        for (int j = 0; j < 8; ++j)
            #pragma unroll
            for (int q = 0; q < 4; ++q)
                acc[i][j][q] = 0.0f;

    // prologue: stages 0 and 1 in flight
    load_stage(sb, 0, 0, tid, tm0, tn0, Ah, Bh);
    asm volatile("cp.async.commit_group;" ::: "memory");
    load_stage(sb, 1, BKF, tid, tm0, tn0, Ah, Bh);
    asm volatile("cp.async.commit_group;" ::: "memory");

    uint32_t aF[2][4][4], bF[2][4][4];

    for (int c = 0; c < NCH; ++c) {
        asm volatile("cp.async.wait_group 1;" ::: "memory");
        __syncthreads();
        // refill the stage read at iter c-1 (c+2 == c-1 mod 3)
        if (c + 2 < NCH)
            load_stage(sb, (c + 2) % NSTAGE, (c + 2) * BKF, tid, tm0, tn0, Ah, Bh);
        asm volatile("cp.async.commit_group;" ::: "memory");

        const uint32_t stg = (uint32_t)(c % NSTAGE) * STAGE;

        // 4 k16 steps, fragments double-buffered: ldsm s+1 issues before mma s
        load_frags(aF[0], bF[0], sb, stg, 0, warp_m, warp_n, lane);
        #pragma unroll
        for (int s = 0; s < 4; ++s) {
            if (s < 3)
                load_frags(aF[(s + 1) & 1], bF[(s + 1) & 1],
                           sb, stg, s + 1, warp_m, warp_n, lane);
            mma_frags(acc, aF[s & 1], bF[s & 1]);
        }
    }

    // epilogue
    const int g = lane >> 2;
    const int t = lane & 3;
    #pragma unroll
    for (int mt = 0; mt < 4; ++mt) {
        #pragma unroll
        for (int nt = 0; nt < 8; ++nt) {
            const int row = tm0 + warp_m * 64 + mt * 16 + g;
            const int col = tn0 + warp_n * 64 + nt * 8 + t * 2;
            *reinterpret_cast<float2*>(Cg + (size_t)row * DDIM + col) =
                make_float2(acc[mt][nt][0], acc[mt][nt][1]);
            *reinterpret_cast<float2*>(Cg + (size_t)(row + 8) * DDIM + col) =
                make_float2(acc[mt][nt][2], acc[mt][nt][3]);
        }
    }
}

extern "C" void kernel_launch(void* const* d_in, const int* in_sizes, int n_in,
                              void* d_out, int out_size) {
    const float* x     = (const float*)d_in[0];
    const int*   steps = (const int*)d_in[1];
    const float* T     = (const float*)d_in[2];
    float* out = (float*)d_out;

    // prepass: fp32 -> fp16 planes (8 elems/thread)
    {
        const size_t nT8 = 100ull * DDIM * DDIM / 8;   // 13,107,200
        const size_t nX8 = 128ull * DDIM * DDIM / 8;   // 16,777,216
        cvt_T_kernel<<<(unsigned)(nT8 / 256), 256>>>(T);
        cvt_X_kernel<<<(unsigned)(nX8 / 256), 256>>>(x);
    }

    cudaFuncSetAttribute(bgemm_mma_kernel,
                         cudaFuncAttributeMaxDynamicSharedMemorySize, SMEM_TOTAL);
    dim3 grid(DDIM / TN, DDIM / TM, 128);  // (4, 8, 128)
    bgemm_mma_kernel<<<grid, 256, SMEM_TOTAL>>>(steps, out);
}

// round 14
// speedup vs baseline: 1.0001x; 1.0001x over previous
#include <cuda_runtime.h>
#include <cuda_fp16.h>
#include <cstdint>

// out[b] = T[fwd_steps[b]-1] @ x[b];  B=128, D=1024, fp32.
// R14: fp16 mma.sync, CTA tile 128x256, warp tile 64x64 (8 warps, 2m x 4n),
// BK=64 (16 barrier rounds), transient ldsm fragments (no reg double-buffer),
// 3-stage cp.async. Prepass converts T,x to fp16 planes (8 elems/thread).

#define DDIM 1024
#define BKF 64
#define NCH (DDIM / BKF)          // 16 chunks
#define NSTAGE 3
#define TM 128
#define TN 256

#define A_STR 144                 // bytes per A smem row (64 fp16 + 16 pad)
#define B_STR 528                 // bytes per B smem row (256 fp16 + 16 pad)
#define B_OFF 18432               // B base within stage (128*144)
#define STAGE 52224               // 18432 + 64*528
#define SMEM_TOTAL (NSTAGE * STAGE)  // 156672

// ---- device scratch: fp16 planes ----
__device__ __align__(16) __half g_Th[100ull * DDIM * DDIM];   // 200 MB
__device__ __align__(16) __half g_Xh[128ull * DDIM * DDIM];   // 256 MB

__device__ __forceinline__ uint32_t smem_u32(const void* p) {
    uint32_t a;
    asm("{ .reg .u64 t; cvta.to.shared.u64 t, %1; cvt.u32.u64 %0, t; }" : "=r"(a) : "l"(p));
    return a;
}
__device__ __forceinline__ void cp16(uint32_t dst, const void* src) {
    asm volatile("cp.async.cg.shared.global [%0], [%1], 16;"
                 :: "r"(dst), "l"(src) : "memory");
}
__device__ __forceinline__ void ldsm4(uint32_t (&r)[4], uint32_t addr) {
    asm volatile("ldmatrix.sync.aligned.m8n8.x4.shared.b16 {%0,%1,%2,%3}, [%4];"
                 : "=r"(r[0]), "=r"(r[1]), "=r"(r[2]), "=r"(r[3]) : "r"(addr));
}
__device__ __forceinline__ void ldsm4t(uint32_t (&r)[4], uint32_t addr) {
    asm volatile("ldmatrix.sync.aligned.m8n8.x4.trans.shared.b16 {%0,%1,%2,%3}, [%4];"
                 : "=r"(r[0]), "=r"(r[1]), "=r"(r[2]), "=r"(r[3]) : "r"(addr));
}
__device__ __forceinline__ void mma_f16(float (&d)[4], const uint32_t (&a)[4],
                                        uint32_t b0, uint32_t b1) {
    asm volatile(
        "mma.sync.aligned.m16n8k16.row.col.f32.f16.f16.f32 "
        "{%0,%1,%2,%3}, {%4,%5,%6,%7}, {%8,%9}, {%0,%1,%2,%3};"
        : "+f"(d[0]), "+f"(d[1]), "+f"(d[2]), "+f"(d[3])
        : "r"(a[0]), "r"(a[1]), "r"(a[2]), "r"(a[3]), "r"(b0), "r"(b1));
}

// ---- prepass: fp32 -> fp16, 8 elems/thread, 16B stores ----
__device__ __forceinline__ uint32_t pack2(float x, float y) {
    __half2 h = __floats2half2_rn(x, y);
    return *reinterpret_cast<uint32_t*>(&h);
}
__global__ __launch_bounds__(256) void cvt_T_kernel(const float* __restrict__ src) {
    const size_t i = (size_t)blockIdx.x * blockDim.x + threadIdx.x;  // 8-elem index
    float4 v0 = *reinterpret_cast<const float4*>(src + 8 * i);
    float4 v1 = *reinterpret_cast<const float4*>(src + 8 * i + 4);
    *reinterpret_cast<uint4*>(g_Th + 8 * i) =
        make_uint4(pack2(v0.x, v0.y), pack2(v0.z, v0.w),
                   pack2(v1.x, v1.y), pack2(v1.z, v1.w));
}
__global__ __launch_bounds__(256) void cvt_X_kernel(const float* __restrict__ src) {
    const size_t i = (size_t)blockIdx.x * blockDim.x + threadIdx.x;
    float4 v0 = *reinterpret_cast<const float4*>(src + 8 * i);
    float4 v1 = *reinterpret_cast<const float4*>(src + 8 * i + 4);
    *reinterpret_cast<uint4*>(g_Xh + 8 * i) =
        make_uint4(pack2(v0.x, v0.y), pack2(v0.z, v0.w),
                   pack2(v1.x, v1.y), pack2(v1.z, v1.w));
}

// ---- main GEMM ----
__device__ __forceinline__ void load_stage(
    uint32_t sb, int stage, int kc, int tid, int tm0, int tn0,
    const __half* __restrict__ Ah, const __half* __restrict__ Bh) {
    const uint32_t base = sb + (uint32_t)stage * STAGE;
    // A: 128 rows x 128B -> 1024 x 16B chunks, 4 per thread
    #pragma unroll
    for (int j = 0; j < 4; ++j) {
        const int i = tid * 4 + j;
        const int row = i >> 3, c16 = i & 7;
        cp16(base + row * A_STR + c16 * 16,
             Ah + (size_t)(tm0 + row) * DDIM + kc + c16 * 8);
    }
    // B: 64 rows x 512B -> 2048 x 16B chunks, 8 per thread
    #pragma unroll
    for (int j = 0; j < 8; ++j) {
        const int i = tid * 8 + j;
        const int row = i >> 5, ch = i & 31;
        cp16(base + B_OFF + row * B_STR + ch * 16,
             Bh + (size_t)(kc + row) * DDIM + tn0 + ch * 8);
    }
}

// one k16 step: 8 ldmatrix + 32 mma (4m x 8n tiles), transient fragments
__device__ __forceinline__ void do_k16(uint32_t sb, uint32_t stg, int k16,
                                       int warp_m, int warp_n, int lane,
                                       float (&acc)[4][8][4]) {
    const uint32_t lrow = lane & 15;
    const uint32_t lsel = lane >> 4;
    const uint32_t a_off = sb + stg + (warp_m * 64 + lrow) * A_STR +
                           (k16 * 16 + lsel * 8) * 2;
    const uint32_t b_off = sb + stg + B_OFF + (k16 * 16 + lrow) * B_STR +
                           (warp_n * 64 + lsel * 8) * 2;

    uint32_t bh[4][4], a[4][4];
    #pragma unroll
    for (int g = 0; g < 4; ++g) ldsm4t(bh[g], b_off + g * 32);
    #pragma unroll
    for (int mt = 0; mt < 4; ++mt) ldsm4(a[mt], a_off + mt * (16 * A_STR));

    #pragma unroll
    for (int mt = 0; mt < 4; ++mt)
        #pragma unroll
        for (int nt = 0; nt < 8; ++nt)
            mma_f16(acc[mt][nt], a[mt],
                    bh[nt >> 1][(nt & 1) * 2], bh[nt >> 1][(nt & 1) * 2 + 1]);
}

__global__ __launch_bounds__(256) void bgemm_mma_kernel(
    const int* __restrict__ steps32,
    float*     __restrict__ Out) {
    extern __shared__ char smem[];
    const uint32_t sb = smem_u32(smem);
    const int tid  = threadIdx.x;
    const int lane = tid & 31;
    const int wid  = tid >> 5;
    const int warp_m = wid & 1;   // 2 warps over M (64 each)
    const int warp_n = wid >> 1;  // 4 warps over N (64 each)

    const int b = blockIdx.z;
    const bool is64 = (steps32[1] == 0);
    const int kidx = (is64 ? steps32[2 * b] : steps32[b]) - 1;

    const __half* __restrict__ Ah = g_Th + ((size_t)kidx << 20);
    const __half* __restrict__ Bh = g_Xh + ((size_t)b << 20);
    float* __restrict__ Cg = Out + ((size_t)b << 20);

    const int tm0 = blockIdx.y * TM;
    const int tn0 = blockIdx.x * TN;

    float acc[4][8][4];
    #pragma unroll
    for (int i = 0; i < 4; ++i)
        #pragma unroll
        for (int j = 0; j < 8; ++j)
            #pragma unroll
            for (int q = 0; q < 4; ++q)
                acc[i][j][q] = 0.0f;

    // prologue: stages 0 and 1 in flight
    load_stage(sb, 0, 0, tid, tm0, tn0, Ah, Bh);
    asm volatile("cp.async.commit_group;" ::: "memory");
    load_stage(sb, 1, BKF, tid, tm0, tn0, Ah, Bh);
    asm volatile("cp.async.commit_group;" ::: "memory");

    for (int c = 0; c < NCH; ++c) {
        asm volatile("cp.async.wait_group 1;" ::: "memory");
        __syncthreads();
        // refill the stage read at iter c-1 (c+2 == c-1 mod 3)
        if (c + 2 < NCH)
            load_stage(sb, (c + 2) % NSTAGE, (c + 2) * BKF, tid, tm0, tn0, Ah, Bh);
        asm volatile("cp.async.commit_group;" ::: "memory");

        const uint32_t stg = (uint32_t)(c % NSTAGE) * STAGE;
        do_k16(sb, stg, 0, warp_m, warp_n, lane, acc);
        do_k16(sb, stg, 1, warp_m, warp_n, lane, acc);
        do_k16(sb, stg, 2, warp_m, warp_n, lane, acc);
        do_k16(sb, stg, 3, warp_m, warp_n, lane, acc);
    }

    // epilogue
    const int g = lane >> 2;
    const int t = lane & 3;
    #pragma unroll
    for (int mt = 0; mt < 4; ++mt) {
        #pragma unroll
        for (int nt = 0; nt < 8; ++nt) {
            const int row = tm0 + warp_m * 64 + mt * 16 + g;
            const int col = tn0 + warp_n * 64 + nt * 8 + t * 2;
            *reinterpret_cast<float2*>(Cg + (size_t)row * DDIM + col) =
                make_float2(acc[mt][nt][0], acc[mt][nt][1]);
            *reinterpret_cast<float2*>(Cg + (size_t)(row + 8) * DDIM + col) =
                make_float2(acc[mt][nt][2], acc[mt][nt][3]);
        }
    }
}

extern "C" void kernel_launch(void* const* d_in, const int* in_sizes, int n_in,
                              void* d_out, int out_size) {
    const float* x     = (const float*)d_in[0];
    const int*   steps = (const int*)d_in[1];
    const float* T     = (const float*)d_in[2];
    float* out = (float*)d_out;

    // prepass: fp32 -> fp16 planes (8 elems/thread)
    {
        const size_t nT8 = 100ull * DDIM * DDIM / 8;   // 13,107,200
        const size_t nX8 = 128ull * DDIM * DDIM / 8;   // 16,777,216
        cvt_T_kernel<<<(unsigned)(nT8 / 256), 256>>>(T);
        cvt_X_kernel<<<(unsigned)(nX8 / 256), 256>>>(x);
    }

    cudaFuncSetAttribute(bgemm_mma_kernel,
                         cudaFuncAttributeMaxDynamicSharedMemorySize, SMEM_TOTAL);
    dim3 grid(DDIM / TN, DDIM / TM, 128);  // (4, 8, 128)
    bgemm_mma_kernel<<<grid, 256, SMEM_TOTAL>>>(steps, out);
}

// round 15
// speedup vs baseline: 1.1497x; 1.1496x over previous
#include <cuda_runtime.h>
#include <cuda_fp16.h>
#include <cstdint>

// out[b] = T[fwd_steps[b]-1] @ x[b];  B=128, D=1024, fp32.
// R15: fp16 mma.sync, CTA tile 256x128, warp tile 64x32, 16 warps (4m x 4n),
// BK=32, 3-stage cp.async. 512 threads -> 4 warps/SMSP for latency hiding.
// Prepass converts T,x to fp16 planes (8 elems/thread).

#define DDIM 1024
#define BKF 32
#define NCH (DDIM / BKF)          // 32 chunks
#define NSTAGE 3
#define TM 256
#define TN 128
#define NT 512

#define A_STR 80                  // bytes per A smem row (32 fp16 + 16 pad)
#define B_STR 272                 // bytes per B smem row (128 fp16 + 16 pad)
#define B_OFF 20480               // B base within stage (256*80)
#define STAGE 29184               // 20480 + 32*272
#define SMEM_TOTAL (NSTAGE * STAGE)  // 87552

// ---- device scratch: fp16 planes ----
__device__ __align__(16) __half g_Th[100ull * DDIM * DDIM];   // 200 MB
__device__ __align__(16) __half g_Xh[128ull * DDIM * DDIM];   // 256 MB

__device__ __forceinline__ uint32_t smem_u32(const void* p) {
    uint32_t a;
    asm("{ .reg .u64 t; cvta.to.shared.u64 t, %1; cvt.u32.u64 %0, t; }" : "=r"(a) : "l"(p));
    return a;
}
__device__ __forceinline__ void cp16(uint32_t dst, const void* src) {
    asm volatile("cp.async.cg.shared.global [%0], [%1], 16;"
                 :: "r"(dst), "l"(src) : "memory");
}
__device__ __forceinline__ void ldsm4(uint32_t (&r)[4], uint32_t addr) {
    asm volatile("ldmatrix.sync.aligned.m8n8.x4.shared.b16 {%0,%1,%2,%3}, [%4];"
                 : "=r"(r[0]), "=r"(r[1]), "=r"(r[2]), "=r"(r[3]) : "r"(addr));
}
__device__ __forceinline__ void ldsm4t(uint32_t (&r)[4], uint32_t addr) {
    asm volatile("ldmatrix.sync.aligned.m8n8.x4.trans.shared.b16 {%0,%1,%2,%3}, [%4];"
                 : "=r"(r[0]), "=r"(r[1]), "=r"(r[2]), "=r"(r[3]) : "r"(addr));
}
__device__ __forceinline__ void mma_f16(float (&d)[4], const uint32_t (&a)[4],
                                        uint32_t b0, uint32_t b1) {
    asm volatile(
        "mma.sync.aligned.m16n8k16.row.col.f32.f16.f16.f32 "
        "{%0,%1,%2,%3}, {%4,%5,%6,%7}, {%8,%9}, {%0,%1,%2,%3};"
        : "+f"(d[0]), "+f"(d[1]), "+f"(d[2]), "+f"(d[3])
        : "r"(a[0]), "r"(a[1]), "r"(a[2]), "r"(a[3]), "r"(b0), "r"(b1));
}

// ---- prepass: fp32 -> fp16, 8 elems/thread, 16B stores ----
__device__ __forceinline__ uint32_t pack2(float x, float y) {
    __half2 h = __floats2half2_rn(x, y);
    return *reinterpret_cast<uint32_t*>(&h);
}
__global__ __launch_bounds__(256) void cvt_T_kernel(const float* __restrict__ src) {
    const size_t i = (size_t)blockIdx.x * blockDim.x + threadIdx.x;  // 8-elem index
    float4 v0 = *reinterpret_cast<const float4*>(src + 8 * i);
    float4 v1 = *reinterpret_cast<const float4*>(src + 8 * i + 4);
    *reinterpret_cast<uint4*>(g_Th + 8 * i) =
        make_uint4(pack2(v0.x, v0.y), pack2(v0.z, v0.w),
                   pack2(v1.x, v1.y), pack2(v1.z, v1.w));
}
__global__ __launch_bounds__(256) void cvt_X_kernel(const float* __restrict__ src) {
    const size_t i = (size_t)blockIdx.x * blockDim.x + threadIdx.x;
    float4 v0 = *reinterpret_cast<const float4*>(src + 8 * i);
    float4 v1 = *reinterpret_cast<const float4*>(src + 8 * i + 4);
    *reinterpret_cast<uint4*>(g_Xh + 8 * i) =
        make_uint4(pack2(v0.x, v0.y), pack2(v0.z, v0.w),
                   pack2(v1.x, v1.y), pack2(v1.z, v1.w));
}

// ---- main GEMM ----
__device__ __forceinline__ void load_stage(
    uint32_t sb, int stage, int kc, int tid, int tm0, int tn0,
    const __half* __restrict__ Ah, const __half* __restrict__ Bh) {
    const uint32_t base = sb + (uint32_t)stage * STAGE;
    // A: 256 rows x 64B -> 1024 x 16B chunks, 2 per thread (512 threads)
    #pragma unroll
    for (int j = 0; j < 2; ++j) {
        const int i = tid * 2 + j;
        const int row = i >> 2, c16 = i & 3;
        cp16(base + row * A_STR + c16 * 16,
             Ah + (size_t)(tm0 + row) * DDIM + kc + c16 * 8);
    }
    // B: 32 rows x 256B -> 512 x 16B chunks, 1 per thread
    {
        const int row = tid >> 4, ch = tid & 15;
        cp16(base + B_OFF + row * B_STR + ch * 16,
             Bh + (size_t)(kc + row) * DDIM + tn0 + ch * 8);
    }
}

// one k16 step: 6 ldmatrix + 16 mma (4m x 4n tiles), transient fragments
__device__ __forceinline__ void do_k16(uint32_t sb, uint32_t stg, int k16,
                                       int warp_m, int warp_n, int lane,
                                       float (&acc)[4][4][4]) {
    const uint32_t lrow = lane & 15;
    const uint32_t lsel = lane >> 4;
    const uint32_t a_off = sb + stg + (warp_m * 64 + lrow) * A_STR +
                           (k16 * 16 + lsel * 8) * 2;
    const uint32_t b_off = sb + stg + B_OFF + (k16 * 16 + lrow) * B_STR +
                           (warp_n * 32 + lsel * 8) * 2;

    uint32_t bh[2][4], a[4][4];
    #pragma unroll
    for (int g = 0; g < 2; ++g) ldsm4t(bh[g], b_off + g * 32);
    #pragma unroll
    for (int mt = 0; mt < 4; ++mt) ldsm4(a[mt], a_off + mt * (16 * A_STR));

    #pragma unroll
    for (int mt = 0; mt < 4; ++mt)
        #pragma unroll
        for (int nt = 0; nt < 4; ++nt)
            mma_f16(acc[mt][nt], a[mt],
                    bh[nt >> 1][(nt & 1) * 2], bh[nt >> 1][(nt & 1) * 2 + 1]);
}

__global__ __launch_bounds__(NT) void bgemm_mma_kernel(
    const int* __restrict__ steps32,
    float*     __restrict__ Out) {
    extern __shared__ char smem[];
    const uint32_t sb = smem_u32(smem);
    const int tid  = threadIdx.x;
    const int lane = tid & 31;
    const int wid  = tid >> 5;
    const int warp_m = wid & 3;   // 4 warps over M (64 each)
    const int warp_n = wid >> 2;  // 4 warps over N (32 each)

    const int b = blockIdx.z;
    const bool is64 = (steps32[1] == 0);
    const int kidx = (is64 ? steps32[2 * b] : steps32[b]) - 1;

    const __half* __restrict__ Ah = g_Th + ((size_t)kidx << 20);
    const __half* __restrict__ Bh = g_Xh + ((size_t)b << 20);
    float* __restrict__ Cg = Out + ((size_t)b << 20);

    const int tm0 = blockIdx.y * TM;
    const int tn0 = blockIdx.x * TN;

    float acc[4][4][4];
    #pragma unroll
    for (int i = 0; i < 4; ++i)
        #pragma unroll
        for (int j = 0; j < 4; ++j)
            #pragma unroll
            for (int q = 0; q < 4; ++q)
                acc[i][j][q] = 0.0f;

    // prologue: stages 0 and 1 in flight
    load_stage(sb, 0, 0, tid, tm0, tn0, Ah, Bh);
    asm volatile("cp.async.commit_group;" ::: "memory");
    load_stage(sb, 1, BKF, tid, tm0, tn0, Ah, Bh);
    asm volatile("cp.async.commit_group;" ::: "memory");

    for (int c = 0; c < NCH; ++c) {
        asm volatile("cp.async.wait_group 1;" ::: "memory");
        __syncthreads();
        // refill the stage read at iter c-1 (c+2 == c-1 mod 3)
        if (c + 2 < NCH)
            load_stage(sb, (c + 2) % NSTAGE, (c + 2) * BKF, tid, tm0, tn0, Ah, Bh);
        asm volatile("cp.async.commit_group;" ::: "memory");

        const uint32_t stg = (uint32_t)(c % NSTAGE) * STAGE;
        do_k16(sb, stg, 0, warp_m, warp_n, lane, acc);
        do_k16(sb, stg, 1, warp_m, warp_n, lane, acc);
    }

    // epilogue
    const int g = lane >> 2;
    const int t = lane & 3;
    #pragma unroll
    for (int mt = 0; mt < 4; ++mt) {
        #pragma unroll
        for (int nt = 0; nt < 4; ++nt) {
            const int row = tm0 + warp_m * 64 + mt * 16 + g;
            const int col = tn0 + warp_n * 32 + nt * 8 + t * 2;
            *reinterpret_cast<float2*>(Cg + (size_t)row * DDIM + col) =
                make_float2(acc[mt][nt][0], acc[mt][nt][1]);
            *reinterpret_cast<float2*>(Cg + (size_t)(row + 8) * DDIM + col) =
                make_float2(acc[mt][nt][2], acc[mt][nt][3]);
        }
    }
}

extern "C" void kernel_launch(void* const* d_in, const int* in_sizes, int n_in,
                              void* d_out, int out_size) {
    const float* x     = (const float*)d_in[0];
    const int*   steps = (const int*)d_in[1];
    const float* T     = (const float*)d_in[2];
    float* out = (float*)d_out;

    // prepass: fp32 -> fp16 planes (8 elems/thread)
    {
        const size_t nT8 = 100ull * DDIM * DDIM / 8;
        const size_t nX8 = 128ull * DDIM * DDIM / 8;
        cvt_T_kernel<<<(unsigned)(nT8 / 256), 256>>>(T);
        cvt_X_kernel<<<(unsigned)(nX8 / 256), 256>>>(x);
    }

    cudaFuncSetAttribute(bgemm_mma_kernel,
                         cudaFuncAttributeMaxDynamicSharedMemorySize, SMEM_TOTAL);
    dim3 grid(DDIM / TN, DDIM / TM, 128);  // (8, 4, 128)
    bgemm_mma_kernel<<<grid, NT, SMEM_TOTAL>>>(steps, out);
}